// round 4
// baseline (speedup 1.0000x reference)
#include <cuda_runtime.h>

// ---------------------------------------------------------------------------
// SoftGatingMoE — routed top-2 MoE (B=4,S=2048,D=1024,E=8,H=1024,top_k=2)
// Round 3: identical to Round 1/2 — both prior rounds died to a broker-level
// "GB300 container failed twice" with zero harness output. Resubmitting the
// verified candidate to obtain the baseline measurement + ncu profile.
// Routed implementation, fp32 SIMT grouped SGEMMs.
// ---------------------------------------------------------------------------

#define NTOK  8192
#define ND    1024
#define NE    8
#define NH    1024
#define NB    4
#define NS    2048
#define NPAIR 16384   // NTOK * top_k

// ---- scratch (static device globals; counters re-zeroed every launch) ----
__device__ float g_tmp1[(size_t)NPAIR * NH];   // x @ w1
__device__ float g_hact[(size_t)NPAIR * NH];   // silu(tmp1) * (x @ w3)
__device__ float g_y  [(size_t)NPAIR * ND];    // hact @ w2 (per-pair expert out)
__device__ int   g_tok[NE * NTOK];             // per-expert token lists
__device__ int   g_cnt[NE];
__device__ int   g_off[NE];
__device__ int   g_mode;                       // 0 = u8 bools, 1 = i32, 2 = f32
__device__ int   g_cntB[NB];
__device__ int   g_pairE[NPAIR];
__device__ int   g_pairPos[NPAIR];
__device__ float g_pairW[NPAIR];
__device__ float g_nonpad[NTOK];
__device__ float g_accE[NE * NB];

__device__ __forceinline__ float siluf(float z) { return z / (1.f + expf(-z)); }

// ---------------------------------------------------------------------------
// init: zero counters + detect mask dtype from raw bytes of tgt_pad.
//   values are only 0/1:
//     u8 storage  -> bytes at (i%4)==1 nonzero somewhere (p=0.3 each)
//     i32 storage -> only (i%4)==0 bytes nonzero
//     f32 storage -> 1.0f = 00 00 80 3F; bytes at (i%4)==0,1 always zero
// ---------------------------------------------------------------------------
__global__ void k_init(const unsigned char* __restrict__ pad_raw)
{
    __shared__ int nz0, nz1;
    int tid = threadIdx.x;
    if (tid == 0) { nz0 = 0; nz1 = 0; }
    __syncthreads();
    int l0 = 0, l1 = 0;
    for (int i = tid; i < NTOK; i += 256) {   // first 8192 bytes: safe for all dtypes
        unsigned char v = pad_raw[i];
        if (v) {
            int m = i & 3;
            if (m == 1) l1 = 1;
            if (m == 0) l0 = 1;
        }
    }
    if (l0) atomicOr(&nz0, 1);
    if (l1) atomicOr(&nz1, 1);
    __syncthreads();
    if (tid == 0) g_mode = nz1 ? 0 : (nz0 ? 1 : 2);
    if (tid < NE) g_cnt[tid] = 0;
    if (tid < NB) g_cntB[tid] = 0;
    if (tid < NE * NB) g_accE[tid] = 0.f;
}

// ---------------------------------------------------------------------------
__global__ void k_mask(const void* __restrict__ p1, const void* __restrict__ p2)
{
    int t = blockIdx.x * 256 + threadIdx.x;
    if (t >= NTOK) return;
    int mode = g_mode;
    bool a, b;
    if (mode == 0) {
        a = ((const unsigned char*)p1)[t] != 0;
        b = ((const unsigned char*)p2)[t] != 0;
    } else if (mode == 1) {
        a = ((const int*)p1)[t] != 0;
        b = ((const int*)p2)[t] != 0;
    } else {
        a = ((const float*)p1)[t] != 0.f;
        b = ((const float*)p2)[t] != 0.f;
    }
    float np = (a || b) ? 0.f : 1.f;
    g_nonpad[t] = np;
    if (np != 0.f) atomicAdd(&g_cntB[t / NS], 1);
}

// ---------------------------------------------------------------------------
// gate: one warp per token. logits = x[t] @ gate_w, softmax(fp32), write
// routing probs, pick top-2, renormalize, scatter into per-expert lists.
// ---------------------------------------------------------------------------
__global__ void __launch_bounds__(256)
k_gate(const float* __restrict__ x, const float* __restrict__ gw,
       float* __restrict__ routing)
{
    int gtid = blockIdx.x * blockDim.x + threadIdx.x;
    int t    = gtid >> 5;
    int lane = threadIdx.x & 31;
    if (t >= NTOK) return;

    const float* xr = x + (size_t)t * ND;
    float acc[8] = {0, 0, 0, 0, 0, 0, 0, 0};
    for (int k = lane; k < ND; k += 32) {
        float xv = xr[k];
        const float4* g4 = (const float4*)(gw + (size_t)k * NE);
        float4 a = g4[0], b = g4[1];
        acc[0] += xv * a.x; acc[1] += xv * a.y; acc[2] += xv * a.z; acc[3] += xv * a.w;
        acc[4] += xv * b.x; acc[5] += xv * b.y; acc[6] += xv * b.z; acc[7] += xv * b.w;
    }
#pragma unroll
    for (int e = 0; e < 8; e++)
#pragma unroll
        for (int o = 16; o > 0; o >>= 1)
            acc[e] += __shfl_xor_sync(0xffffffffu, acc[e], o);

    if (lane == 0) {
        float mx = acc[0];
#pragma unroll
        for (int e = 1; e < 8; e++) mx = fmaxf(mx, acc[e]);
        float p[8], s = 0.f;
#pragma unroll
        for (int e = 0; e < 8; e++) { p[e] = expf(acc[e] - mx); s += p[e]; }
        float inv = 1.f / s;
#pragma unroll
        for (int e = 0; e < 8; e++) { p[e] *= inv; routing[(size_t)t * NE + e] = p[e]; }

        int i1 = 0;
#pragma unroll
        for (int e = 1; e < 8; e++) if (p[e] > p[i1]) i1 = e;
        int i2 = (i1 == 0) ? 1 : 0;
#pragma unroll
        for (int e = 0; e < 8; e++) if (e != i1 && p[e] > p[i2]) i2 = e;

        float v1 = p[i1], v2 = p[i2];
        float rinv = 1.f / (v1 + v2);
        int pos1 = atomicAdd(&g_cnt[i1], 1);
        g_tok[i1 * NTOK + pos1] = t;
        g_pairE[2 * t] = i1; g_pairPos[2 * t] = pos1; g_pairW[2 * t] = v1 * rinv;
        int pos2 = atomicAdd(&g_cnt[i2], 1);
        g_tok[i2 * NTOK + pos2] = t;
        g_pairE[2 * t + 1] = i2; g_pairPos[2 * t + 1] = pos2; g_pairW[2 * t + 1] = v2 * rinv;
    }
}

// ---------------------------------------------------------------------------
__global__ void k_off()
{
    if (threadIdx.x == 0) {
        int s = 0;
        for (int e = 0; e < NE; e++) { g_off[e] = s; s += g_cnt[e]; }
    }
}

// ---------------------------------------------------------------------------
// Grouped SGEMM: 128x128x8 tiles, 256 threads, 8x8 microtile, double-buffered.
// PHASE 0: C = gather(x) @ w1[e]            -> g_tmp1
// PHASE 1: C = gather(x) @ w3[e]; epilogue  -> g_hact = silu(g_tmp1)*C
// PHASE 2: C = g_hact    @ w2[e]            -> g_y   (A operand = g_hact)
// grid = (N/128, 64, E); blocks past the expert's row count exit.
// ---------------------------------------------------------------------------
template <int PHASE>
__global__ void __launch_bounds__(256, 2)
k_gemm(const float* __restrict__ A, const float* __restrict__ W)
{
    const int e   = blockIdx.z;
    const int cnt = g_cnt[e];
    const int m0  = blockIdx.y * 128;
    if (m0 >= cnt) return;
    const int n0   = blockIdx.x * 128;
    const int base = g_off[e];

    __shared__ float As[2][8][128];
    __shared__ float Bs[2][8][128];

    const int tid = threadIdx.x;
    const int ar  = tid >> 1;
    const int aq  = (tid & 1) * 4;
    const int bk  = tid >> 5;
    const int bc  = (tid & 31) * 4;

    const int  arow = m0 + ar;
    const bool aval = arow < cnt;

    const float* Aptr;
    if (PHASE == 2) {
        Aptr = g_hact + (size_t)(base + (aval ? arow : 0)) * NH + aq;
    } else {
        int tok = aval ? g_tok[e * NTOK + arow] : 0;
        Aptr = A + (size_t)tok * ND + aq;
    }
    const float* Bptr = W + (size_t)e * ND * NH + (size_t)bk * 1024 + n0 + bc;

    float4 av = aval ? *(const float4*)Aptr : make_float4(0.f, 0.f, 0.f, 0.f);
    float4 bv = *(const float4*)Bptr;
    As[0][aq + 0][ar] = av.x; As[0][aq + 1][ar] = av.y;
    As[0][aq + 2][ar] = av.z; As[0][aq + 3][ar] = av.w;
    *(float4*)&Bs[0][bk][bc] = bv;
    __syncthreads();

    const int ty = (tid >> 4) * 8;
    const int tx = (tid & 15) * 8;

    float acc[8][8];
#pragma unroll
    for (int i = 0; i < 8; i++)
#pragma unroll
        for (int j = 0; j < 8; j++) acc[i][j] = 0.f;

    int buf = 0;
    for (int k0 = 8; k0 <= 1024; k0 += 8) {
        float4 nav, nbv;
        if (k0 < 1024) {
            nav = aval ? *(const float4*)(Aptr + k0) : make_float4(0.f, 0.f, 0.f, 0.f);
            nbv = *(const float4*)(Bptr + (size_t)k0 * 1024);
        }
#pragma unroll
        for (int kk = 0; kk < 8; kk++) {
            float a[8], b[8];
            *(float4*)&a[0] = *(const float4*)&As[buf][kk][ty];
            *(float4*)&a[4] = *(const float4*)&As[buf][kk][ty + 4];
            *(float4*)&b[0] = *(const float4*)&Bs[buf][kk][tx];
            *(float4*)&b[4] = *(const float4*)&Bs[buf][kk][tx + 4];
#pragma unroll
            for (int i = 0; i < 8; i++)
#pragma unroll
                for (int j = 0; j < 8; j++)
                    acc[i][j] = fmaf(a[i], b[j], acc[i][j]);
        }
        if (k0 < 1024) {
            int nb = buf ^ 1;
            As[nb][aq + 0][ar] = nav.x; As[nb][aq + 1][ar] = nav.y;
            As[nb][aq + 2][ar] = nav.z; As[nb][aq + 3][ar] = nav.w;
            *(float4*)&Bs[nb][bk][bc] = nbv;
        }
        __syncthreads();
        buf ^= 1;
    }

#pragma unroll
    for (int i = 0; i < 8; i++) {
        int r = m0 + ty + i;
        if (r < cnt) {
            size_t off = (size_t)(base + r) * 1024 + n0 + tx;
            float4 v0 = make_float4(acc[i][0], acc[i][1], acc[i][2], acc[i][3]);
            float4 v1 = make_float4(acc[i][4], acc[i][5], acc[i][6], acc[i][7]);
            if (PHASE == 0) {
                *(float4*)&g_tmp1[off]     = v0;
                *(float4*)&g_tmp1[off + 4] = v1;
            } else if (PHASE == 1) {
                float4 c0 = *(const float4*)&g_tmp1[off];
                float4 c1 = *(const float4*)&g_tmp1[off + 4];
                v0.x *= siluf(c0.x); v0.y *= siluf(c0.y);
                v0.z *= siluf(c0.z); v0.w *= siluf(c0.w);
                v1.x *= siluf(c1.x); v1.y *= siluf(c1.y);
                v1.z *= siluf(c1.z); v1.w *= siluf(c1.w);
                *(float4*)&g_hact[off]     = v0;
                *(float4*)&g_hact[off + 4] = v1;
            } else {
                *(float4*)&g_y[off]     = v0;
                *(float4*)&g_y[off + 4] = v1;
            }
        }
    }
}

// ---------------------------------------------------------------------------
// combine: final[t] = w0*y[r0] + w1*y[r1]; also per-pair dot with clf_w,
// accumulated (weighted, nonpad-masked) into g_accE[e][batch].
// ---------------------------------------------------------------------------
__global__ void __launch_bounds__(256)
k_combine(float* __restrict__ outF, const float* __restrict__ clfw)
{
    int t = blockIdx.x, tid = threadIdx.x;
    int e0 = g_pairE[2 * t], e1 = g_pairE[2 * t + 1];
    size_t r0 = (size_t)(g_off[e0] + g_pairPos[2 * t]);
    size_t r1 = (size_t)(g_off[e1] + g_pairPos[2 * t + 1]);
    float w0 = g_pairW[2 * t], w1 = g_pairW[2 * t + 1];

    float4 a = *(const float4*)&g_y[r0 * 1024 + tid * 4];
    float4 b = *(const float4*)&g_y[r1 * 1024 + tid * 4];
    float4 c = *(const float4*)&clfw[tid * 4];

    float4 f;
    f.x = w0 * a.x + w1 * b.x;
    f.y = w0 * a.y + w1 * b.y;
    f.z = w0 * a.z + w1 * b.z;
    f.w = w0 * a.w + w1 * b.w;
    *(float4*)&outF[(size_t)t * 1024 + tid * 4] = f;

    float s0 = a.x * c.x + a.y * c.y + a.z * c.z + a.w * c.w;
    float s1 = b.x * c.x + b.y * c.y + b.z * c.z + b.w * c.w;
#pragma unroll
    for (int o = 16; o > 0; o >>= 1) {
        s0 += __shfl_xor_sync(0xffffffffu, s0, o);
        s1 += __shfl_xor_sync(0xffffffffu, s1, o);
    }
    __shared__ float red0[8], red1[8];
    if ((tid & 31) == 0) { red0[tid >> 5] = s0; red1[tid >> 5] = s1; }
    __syncthreads();
    if (tid == 0) {
        float t0 = 0.f, t1 = 0.f;
#pragma unroll
        for (int w = 0; w < 8; w++) { t0 += red0[w]; t1 += red1[w]; }
        float np = g_nonpad[t];
        if (np > 0.f) {
            int bb = t >> 11;   // t / 2048
            atomicAdd(&g_accE[e0 * NB + bb], w0 * t0);
            atomicAdd(&g_accE[e1 * NB + bb], w1 * t1);
        }
    }
}

// ---------------------------------------------------------------------------
__global__ void k_logits(float* __restrict__ outL, const float* __restrict__ clfb)
{
    if (threadIdx.x == 0) {
        float bias = clfb[0];
        for (int b = 0; b < NB; b++) {
            float inv = 1.f / (float)g_cntB[b];
            float run = 0.f;
            for (int e = 0; e < NE; e++) {
                run += g_accE[e * NB + b];
                outL[e * NB + b] = run * inv + bias;   // [E,B,1] layout
            }
        }
    }
}

// ---------------------------------------------------------------------------
extern "C" void kernel_launch(void* const* d_in, const int* in_sizes, int n_in,
                              void* d_out, int out_size)
{
    // Robust input indexing: the scalar top_k may or may not appear as an
    // input. If present it sits at slot 3 with size 1; otherwise slot 3 is
    // gate_w (8192 elements).
    int sh = 0;
    if (n_in >= 10 && in_sizes[3] == 1) sh = 1;

    const float* x    = (const float*)d_in[0];
    const void*  pad  = d_in[1];
    const void*  mid  = d_in[2];
    const float* gw   = (const float*)d_in[3 + sh];
    const float* w1   = (const float*)d_in[4 + sh];
    const float* w2   = (const float*)d_in[5 + sh];
    const float* w3   = (const float*)d_in[6 + sh];
    const float* clfw = (const float*)d_in[7 + sh];
    const float* clfb = (const float*)d_in[8 + sh];

    float* out  = (float*)d_out;
    float* outF = out;                                   // [B,S,D]
    float* outL = out + (size_t)NTOK * ND;               // [E,B,1]
    float* outR = outL + NE * NB;                        // [B,S,E]

    k_init<<<1, 256>>>((const unsigned char*)pad);
    k_mask<<<NTOK / 256, 256>>>(pad, mid);
    k_gate<<<NTOK / 8, 256>>>(x, gw, outR);
    k_off<<<1, 32>>>();

    dim3 g(NH / 128, NTOK / 128, NE);
    k_gemm<0><<<g, 256>>>(x, w1);
    k_gemm<1><<<g, 256>>>(x, w3);
    dim3 g2(ND / 128, NTOK / 128, NE);
    k_gemm<2><<<g2, 256>>>(nullptr, w2);

    k_combine<<<NTOK, 256>>>(outF, clfw);
    k_logits<<<1, 32>>>(outL, clfb);

    (void)in_sizes; (void)n_in; (void)out_size;
}

// round 6
// speedup vs baseline: 1.8573x; 1.8573x over previous
#include <cuda_runtime.h>
#include <cuda_bf16.h>
#include <cstdint>

typedef unsigned int u32;

// ---------------------------------------------------------------------------
// SoftGatingMoE — routed top-2 MoE (B=4,S=2048,D=1024,E=8,H=1024,top_k=2)
// Round 5: Round-4 tensor-core GEMM with the uint32_t/<cstdint> compile fix
// (all new code uses a local u32 typedef). Gate stays exact fp32.
// ---------------------------------------------------------------------------

#define NTOK  8192
#define ND    1024
#define NE    8
#define NH    1024
#define NB    4
#define NS    2048
#define NPAIR 16384   // NTOK * top_k

// ---- scratch (static device globals; counters re-zeroed every launch) ----
__device__ float g_tmp1[(size_t)NPAIR * NH];   // x @ w1
__device__ float g_hact[(size_t)NPAIR * NH];   // silu(tmp1) * (x @ w3)
__device__ float g_y  [(size_t)NPAIR * ND];    // hact @ w2 (per-pair expert out)
__device__ int   g_tok[NE * NTOK];             // per-expert token lists
__device__ int   g_cnt[NE];
__device__ int   g_off[NE];
__device__ int   g_mode;                       // 0 = u8 bools, 1 = i32, 2 = f32
__device__ int   g_cntB[NB];
__device__ int   g_pairE[NPAIR];
__device__ int   g_pairPos[NPAIR];
__device__ float g_pairW[NPAIR];
__device__ float g_nonpad[NTOK];
__device__ float g_accE[NE * NB];

__device__ __forceinline__ float siluf(float z) { return z / (1.f + expf(-z)); }

// ---------------------------------------------------------------------------
// init: zero counters + detect mask dtype from raw bytes of tgt_pad.
// ---------------------------------------------------------------------------
__global__ void k_init(const unsigned char* __restrict__ pad_raw)
{
    __shared__ int nz0, nz1;
    int tid = threadIdx.x;
    if (tid == 0) { nz0 = 0; nz1 = 0; }
    __syncthreads();
    int l0 = 0, l1 = 0;
    for (int i = tid; i < NTOK; i += 256) {
        unsigned char v = pad_raw[i];
        if (v) {
            int m = i & 3;
            if (m == 1) l1 = 1;
            if (m == 0) l0 = 1;
        }
    }
    if (l0) atomicOr(&nz0, 1);
    if (l1) atomicOr(&nz1, 1);
    __syncthreads();
    if (tid == 0) g_mode = nz1 ? 0 : (nz0 ? 1 : 2);
    if (tid < NE) g_cnt[tid] = 0;
    if (tid < NB) g_cntB[tid] = 0;
    if (tid < NE * NB) g_accE[tid] = 0.f;
}

// ---------------------------------------------------------------------------
__global__ void k_mask(const void* __restrict__ p1, const void* __restrict__ p2)
{
    int t = blockIdx.x * 256 + threadIdx.x;
    if (t >= NTOK) return;
    int mode = g_mode;
    bool a, b;
    if (mode == 0) {
        a = ((const unsigned char*)p1)[t] != 0;
        b = ((const unsigned char*)p2)[t] != 0;
    } else if (mode == 1) {
        a = ((const int*)p1)[t] != 0;
        b = ((const int*)p2)[t] != 0;
    } else {
        a = ((const float*)p1)[t] != 0.f;
        b = ((const float*)p2)[t] != 0.f;
    }
    float np = (a || b) ? 0.f : 1.f;
    g_nonpad[t] = np;
    if (np != 0.f) atomicAdd(&g_cntB[t / NS], 1);
}

// ---------------------------------------------------------------------------
// gate: exact fp32 so top-k selection matches the reference bit-for-bit.
// ---------------------------------------------------------------------------
__global__ void __launch_bounds__(256)
k_gate(const float* __restrict__ x, const float* __restrict__ gw,
       float* __restrict__ routing)
{
    int gtid = blockIdx.x * blockDim.x + threadIdx.x;
    int t    = gtid >> 5;
    int lane = threadIdx.x & 31;
    if (t >= NTOK) return;

    const float* xr = x + (size_t)t * ND;
    float acc[8] = {0, 0, 0, 0, 0, 0, 0, 0};
    for (int k = lane; k < ND; k += 32) {
        float xv = xr[k];
        const float4* g4 = (const float4*)(gw + (size_t)k * NE);
        float4 a = g4[0], b = g4[1];
        acc[0] += xv * a.x; acc[1] += xv * a.y; acc[2] += xv * a.z; acc[3] += xv * a.w;
        acc[4] += xv * b.x; acc[5] += xv * b.y; acc[6] += xv * b.z; acc[7] += xv * b.w;
    }
#pragma unroll
    for (int e = 0; e < 8; e++)
#pragma unroll
        for (int o = 16; o > 0; o >>= 1)
            acc[e] += __shfl_xor_sync(0xffffffffu, acc[e], o);

    if (lane == 0) {
        float mx = acc[0];
#pragma unroll
        for (int e = 1; e < 8; e++) mx = fmaxf(mx, acc[e]);
        float p[8], s = 0.f;
#pragma unroll
        for (int e = 0; e < 8; e++) { p[e] = expf(acc[e] - mx); s += p[e]; }
        float inv = 1.f / s;
#pragma unroll
        for (int e = 0; e < 8; e++) { p[e] *= inv; routing[(size_t)t * NE + e] = p[e]; }

        int i1 = 0;
#pragma unroll
        for (int e = 1; e < 8; e++) if (p[e] > p[i1]) i1 = e;
        int i2 = (i1 == 0) ? 1 : 0;
#pragma unroll
        for (int e = 0; e < 8; e++) if (e != i1 && p[e] > p[i2]) i2 = e;

        float v1 = p[i1], v2 = p[i2];
        float rinv = 1.f / (v1 + v2);
        int pos1 = atomicAdd(&g_cnt[i1], 1);
        g_tok[i1 * NTOK + pos1] = t;
        g_pairE[2 * t] = i1; g_pairPos[2 * t] = pos1; g_pairW[2 * t] = v1 * rinv;
        int pos2 = atomicAdd(&g_cnt[i2], 1);
        g_tok[i2 * NTOK + pos2] = t;
        g_pairE[2 * t + 1] = i2; g_pairPos[2 * t + 1] = pos2; g_pairW[2 * t + 1] = v2 * rinv;
    }
}

// ---------------------------------------------------------------------------
__global__ void k_off()
{
    if (threadIdx.x == 0) {
        int s = 0;
        for (int e = 0; e < NE; e++) { g_off[e] = s; s += g_cnt[e]; }
    }
}

// ---------------------------------------------------------------------------
// Tensor-core grouped GEMM, bf16 split (hi+lo), mma.sync m16n8k16.
// Tile 128x128, BK=16, 256 threads = 8 warps, each warp 64x32.
// PHASE 0: C = gather(x) @ w1[e]            -> g_tmp1
// PHASE 1: C = gather(x) @ w3[e]; epilogue  -> g_hact = silu(g_tmp1)*C
// PHASE 2: C = g_hact    @ w2[e]            -> g_y
// ---------------------------------------------------------------------------
__device__ __forceinline__ u32 s2u(const void* p)
{
    return (u32)__cvta_generic_to_shared(p);
}

__device__ __forceinline__ void ldsm4(u32* r, u32 addr)
{
    asm volatile("ldmatrix.sync.aligned.m8n8.x4.shared.b16 {%0,%1,%2,%3}, [%4];"
                 : "=r"(r[0]), "=r"(r[1]), "=r"(r[2]), "=r"(r[3]) : "r"(addr));
}

__device__ __forceinline__ void ldsm4t(u32* r, u32 addr)
{
    asm volatile("ldmatrix.sync.aligned.m8n8.x4.trans.shared.b16 {%0,%1,%2,%3}, [%4];"
                 : "=r"(r[0]), "=r"(r[1]), "=r"(r[2]), "=r"(r[3]) : "r"(addr));
}

__device__ __forceinline__ void mma_bf16(float* c, const u32* a, const u32* b)
{
    asm volatile("mma.sync.aligned.m16n8k16.row.col.f32.bf16.bf16.f32 "
                 "{%0,%1,%2,%3},{%4,%5,%6,%7},{%8,%9},{%0,%1,%2,%3};"
                 : "+f"(c[0]), "+f"(c[1]), "+f"(c[2]), "+f"(c[3])
                 : "r"(a[0]), "r"(a[1]), "r"(a[2]), "r"(a[3]), "r"(b[0]), "r"(b[1]));
}

// Split (a,b) fp32 pair into packed bf16x2 hi and lo (residual) words.
__device__ __forceinline__ void split2(float a, float b, u32& hi, u32& lo)
{
    __nv_bfloat16 ah = __float2bfloat16(a);
    __nv_bfloat16 bh = __float2bfloat16(b);
    float ar = a - __bfloat162float(ah);
    float br = b - __bfloat162float(bh);
    __nv_bfloat162 h; h.x = ah; h.y = bh;
    __nv_bfloat162 l; l.x = __float2bfloat16(ar); l.y = __float2bfloat16(br);
    hi = *(u32*)&h;
    lo = *(u32*)&l;
}

#define A_STR 24    // bf16 elements per A smem row (16 data + 8 pad) -> 48B
#define B_STR 136   // bf16 elements per B smem row (128 data + 8 pad) -> 272B

template <int PHASE>
__global__ void __launch_bounds__(256, 1)
k_gemm_tc(const float* __restrict__ A, const float* __restrict__ W)
{
    const int e   = blockIdx.z;
    const int cnt = g_cnt[e];
    const int m0  = blockIdx.y * 128;
    if (m0 >= cnt) return;
    const int n0t  = blockIdx.x * 128;
    const int base = g_off[e];

    __shared__ __nv_bfloat16 Ah[2][128][A_STR];
    __shared__ __nv_bfloat16 Al[2][128][A_STR];
    __shared__ __nv_bfloat16 Bh[2][16][B_STR];
    __shared__ __nv_bfloat16 Bl[2][16][B_STR];

    const int tid = threadIdx.x;

    // ---- global load mapping ----
    const int ar   = tid >> 1;        // A row 0..127
    const int ak   = (tid & 1) * 8;   // A k offset 0/8 (two float4 each)
    const int arow = m0 + ar;
    const bool aval = arow < cnt;
    const float* Aptr;
    if (PHASE == 2) {
        Aptr = g_hact + (size_t)(base + (aval ? arow : 0)) * NH + ak;
    } else {
        int tok = aval ? g_tok[e * NTOK + arow] : 0;
        Aptr = A + (size_t)tok * ND + ak;
    }
    const int bkr = tid >> 4;          // B k row 0..15
    const int bn  = (tid & 15) * 8;    // B n offset (two float4)
    const float* Bptr = W + (size_t)e * ND * NH + (size_t)bkr * 1024 + n0t + bn;

    // ---- fragment addressing ----
    const int wid  = tid >> 5, lane = tid & 31;
    const int wm   = (wid & 1) * 64;       // warp tile m offset
    const int wn   = (wid >> 1) * 32;      // warp tile n offset
    const int lrow = lane & 15;
    const int lseg = (lane >> 4) * 8;

    float acc[4][4][4];
#pragma unroll
    for (int i = 0; i < 4; i++)
#pragma unroll
        for (int j = 0; j < 4; j++)
#pragma unroll
            for (int q = 0; q < 4; q++) acc[i][j][q] = 0.f;

    float4 av0, av1, bv0, bv1;

    // prologue: load k-stage 0
    av0 = aval ? *(const float4*)(Aptr + 0) : make_float4(0.f, 0.f, 0.f, 0.f);
    av1 = aval ? *(const float4*)(Aptr + 4) : make_float4(0.f, 0.f, 0.f, 0.f);
    bv0 = *(const float4*)(Bptr + 0);
    bv1 = *(const float4*)(Bptr + 4);
    {
        u32 h0, l0, h1, l1;
        split2(av0.x, av0.y, h0, l0); split2(av0.z, av0.w, h1, l1);
        *(uint2*)&Ah[0][ar][ak]     = make_uint2(h0, h1);
        *(uint2*)&Al[0][ar][ak]     = make_uint2(l0, l1);
        split2(av1.x, av1.y, h0, l0); split2(av1.z, av1.w, h1, l1);
        *(uint2*)&Ah[0][ar][ak + 4] = make_uint2(h0, h1);
        *(uint2*)&Al[0][ar][ak + 4] = make_uint2(l0, l1);
        split2(bv0.x, bv0.y, h0, l0); split2(bv0.z, bv0.w, h1, l1);
        *(uint2*)&Bh[0][bkr][bn]     = make_uint2(h0, h1);
        *(uint2*)&Bl[0][bkr][bn]     = make_uint2(l0, l1);
        split2(bv1.x, bv1.y, h0, l0); split2(bv1.z, bv1.w, h1, l1);
        *(uint2*)&Bh[0][bkr][bn + 4] = make_uint2(h0, h1);
        *(uint2*)&Bl[0][bkr][bn + 4] = make_uint2(l0, l1);
    }
    __syncthreads();

    for (int ks = 0; ks < 64; ks++) {
        const int buf = ks & 1;
        if (ks < 63) {
            const int ko = (ks + 1) * 16;
            av0 = aval ? *(const float4*)(Aptr + ko)     : make_float4(0.f, 0.f, 0.f, 0.f);
            av1 = aval ? *(const float4*)(Aptr + ko + 4) : make_float4(0.f, 0.f, 0.f, 0.f);
            bv0 = *(const float4*)(Bptr + (size_t)ko * 1024);
            bv1 = *(const float4*)(Bptr + (size_t)ko * 1024 + 4);
        }

        // ---- fragments ----
        u32 fa_h[4][4], fa_l[4][4];
#pragma unroll
        for (int i = 0; i < 4; i++) {
            ldsm4(fa_h[i], s2u(&Ah[buf][wm + 16 * i + lrow][lseg]));
            ldsm4(fa_l[i], s2u(&Al[buf][wm + 16 * i + lrow][lseg]));
        }
        u32 fb_h[4][2], fb_l[4][2];
#pragma unroll
        for (int jj = 0; jj < 2; jj++) {
            u32 r[4];
            ldsm4t(r, s2u(&Bh[buf][lrow][wn + jj * 16 + lseg]));
            fb_h[2 * jj][0] = r[0]; fb_h[2 * jj][1] = r[1];
            fb_h[2 * jj + 1][0] = r[2]; fb_h[2 * jj + 1][1] = r[3];
            ldsm4t(r, s2u(&Bl[buf][lrow][wn + jj * 16 + lseg]));
            fb_l[2 * jj][0] = r[0]; fb_l[2 * jj][1] = r[1];
            fb_l[2 * jj + 1][0] = r[2]; fb_l[2 * jj + 1][1] = r[3];
        }

        // ---- 3-term split mma ----
#pragma unroll
        for (int i = 0; i < 4; i++)
#pragma unroll
            for (int j = 0; j < 4; j++) {
                mma_bf16(acc[i][j], fa_h[i], fb_h[j]);
                mma_bf16(acc[i][j], fa_h[i], fb_l[j]);
                mma_bf16(acc[i][j], fa_l[i], fb_h[j]);
            }

        if (ks < 63) {
            const int nb = buf ^ 1;
            u32 h0, l0, h1, l1;
            split2(av0.x, av0.y, h0, l0); split2(av0.z, av0.w, h1, l1);
            *(uint2*)&Ah[nb][ar][ak]     = make_uint2(h0, h1);
            *(uint2*)&Al[nb][ar][ak]     = make_uint2(l0, l1);
            split2(av1.x, av1.y, h0, l0); split2(av1.z, av1.w, h1, l1);
            *(uint2*)&Ah[nb][ar][ak + 4] = make_uint2(h0, h1);
            *(uint2*)&Al[nb][ar][ak + 4] = make_uint2(l0, l1);
            split2(bv0.x, bv0.y, h0, l0); split2(bv0.z, bv0.w, h1, l1);
            *(uint2*)&Bh[nb][bkr][bn]     = make_uint2(h0, h1);
            *(uint2*)&Bl[nb][bkr][bn]     = make_uint2(l0, l1);
            split2(bv1.x, bv1.y, h0, l0); split2(bv1.z, bv1.w, h1, l1);
            *(uint2*)&Bh[nb][bkr][bn + 4] = make_uint2(h0, h1);
            *(uint2*)&Bl[nb][bkr][bn + 4] = make_uint2(l0, l1);
        }
        __syncthreads();
    }

    // ---- epilogue ----
    const int crow = lane >> 2;
    const int ccol = (lane & 3) * 2;
#pragma unroll
    for (int i = 0; i < 4; i++) {
        int r0 = m0 + wm + 16 * i + crow;
        int r1 = r0 + 8;
#pragma unroll
        for (int j = 0; j < 4; j++) {
            int c = n0t + wn + 8 * j + ccol;
            if (r0 < cnt) {
                size_t off = (size_t)(base + r0) * 1024 + c;
                float2 v = make_float2(acc[i][j][0], acc[i][j][1]);
                if (PHASE == 0) {
                    *(float2*)&g_tmp1[off] = v;
                } else if (PHASE == 1) {
                    float2 t1 = *(const float2*)&g_tmp1[off];
                    v.x *= siluf(t1.x); v.y *= siluf(t1.y);
                    *(float2*)&g_hact[off] = v;
                } else {
                    *(float2*)&g_y[off] = v;
                }
            }
            if (r1 < cnt) {
                size_t off = (size_t)(base + r1) * 1024 + c;
                float2 v = make_float2(acc[i][j][2], acc[i][j][3]);
                if (PHASE == 0) {
                    *(float2*)&g_tmp1[off] = v;
                } else if (PHASE == 1) {
                    float2 t1 = *(const float2*)&g_tmp1[off];
                    v.x *= siluf(t1.x); v.y *= siluf(t1.y);
                    *(float2*)&g_hact[off] = v;
                } else {
                    *(float2*)&g_y[off] = v;
                }
            }
        }
    }
}

// ---------------------------------------------------------------------------
// combine: final[t] = w0*y[r0] + w1*y[r1]; plus per-pair clf dots into g_accE.
// ---------------------------------------------------------------------------
__global__ void __launch_bounds__(256)
k_combine(float* __restrict__ outF, const float* __restrict__ clfw)
{
    int t = blockIdx.x, tid = threadIdx.x;
    int e0 = g_pairE[2 * t], e1 = g_pairE[2 * t + 1];
    size_t r0 = (size_t)(g_off[e0] + g_pairPos[2 * t]);
    size_t r1 = (size_t)(g_off[e1] + g_pairPos[2 * t + 1]);
    float w0 = g_pairW[2 * t], w1 = g_pairW[2 * t + 1];

    float4 a = *(const float4*)&g_y[r0 * 1024 + tid * 4];
    float4 b = *(const float4*)&g_y[r1 * 1024 + tid * 4];
    float4 c = *(const float4*)&clfw[tid * 4];

    float4 f;
    f.x = w0 * a.x + w1 * b.x;
    f.y = w0 * a.y + w1 * b.y;
    f.z = w0 * a.z + w1 * b.z;
    f.w = w0 * a.w + w1 * b.w;
    *(float4*)&outF[(size_t)t * 1024 + tid * 4] = f;

    float s0 = a.x * c.x + a.y * c.y + a.z * c.z + a.w * c.w;
    float s1 = b.x * c.x + b.y * c.y + b.z * c.z + b.w * c.w;
#pragma unroll
    for (int o = 16; o > 0; o >>= 1) {
        s0 += __shfl_xor_sync(0xffffffffu, s0, o);
        s1 += __shfl_xor_sync(0xffffffffu, s1, o);
    }
    __shared__ float red0[8], red1[8];
    if ((tid & 31) == 0) { red0[tid >> 5] = s0; red1[tid >> 5] = s1; }
    __syncthreads();
    if (tid == 0) {
        float t0 = 0.f, t1 = 0.f;
#pragma unroll
        for (int w = 0; w < 8; w++) { t0 += red0[w]; t1 += red1[w]; }
        float np = g_nonpad[t];
        if (np > 0.f) {
            int bb = t >> 11;   // t / 2048
            atomicAdd(&g_accE[e0 * NB + bb], w0 * t0);
            atomicAdd(&g_accE[e1 * NB + bb], w1 * t1);
        }
    }
}

// ---------------------------------------------------------------------------
__global__ void k_logits(float* __restrict__ outL, const float* __restrict__ clfb)
{
    if (threadIdx.x == 0) {
        float bias = clfb[0];
        for (int b = 0; b < NB; b++) {
            float inv = 1.f / (float)g_cntB[b];
            float run = 0.f;
            for (int e = 0; e < NE; e++) {
                run += g_accE[e * NB + b];
                outL[e * NB + b] = run * inv + bias;   // [E,B,1] layout
            }
        }
    }
}

// ---------------------------------------------------------------------------
extern "C" void kernel_launch(void* const* d_in, const int* in_sizes, int n_in,
                              void* d_out, int out_size)
{
    // The scalar top_k may or may not appear as an input; detect from sizes.
    int sh = 0;
    if (n_in >= 10 && in_sizes[3] == 1) sh = 1;

    const float* x    = (const float*)d_in[0];
    const void*  pad  = d_in[1];
    const void*  mid  = d_in[2];
    const float* gw   = (const float*)d_in[3 + sh];
    const float* w1   = (const float*)d_in[4 + sh];
    const float* w2   = (const float*)d_in[5 + sh];
    const float* w3   = (const float*)d_in[6 + sh];
    const float* clfw = (const float*)d_in[7 + sh];
    const float* clfb = (const float*)d_in[8 + sh];

    float* out  = (float*)d_out;
    float* outF = out;                                   // [B,S,D]
    float* outL = out + (size_t)NTOK * ND;               // [E,B,1]
    float* outR = outL + NE * NB;                        // [B,S,E]

    k_init<<<1, 256>>>((const unsigned char*)pad);
    k_mask<<<NTOK / 256, 256>>>(pad, mid);
    k_gate<<<NTOK / 8, 256>>>(x, gw, outR);
    k_off<<<1, 32>>>();

    dim3 g(NH / 128, NTOK / 128, NE);
    k_gemm_tc<0><<<g, 256>>>(x, w1);
    k_gemm_tc<1><<<g, 256>>>(x, w3);
    dim3 g2(ND / 128, NTOK / 128, NE);
    k_gemm_tc<2><<<g2, 256>>>(nullptr, w2);

    k_combine<<<NTOK, 256>>>(outF, clfw);
    k_logits<<<1, 32>>>(outL, clfb);

    (void)in_sizes; (void)n_in; (void)out_size;
}